// round 8
// baseline (speedup 1.0000x reference)
#include <cuda_runtime.h>

// GRAPE: 20 commuting X-rotations collapse to one rotation, Theta = sum(a)*DT/2.
// 256 MiB pure stream at the mixed-R/W HBM roofline (~6.2 TB/s effective).
//
// R7 -> R8: pair assignment interleaved at even/odd block granularity
// (instead of low-half/high-half of the grid), so every scheduling wave
// drives a uniform blend of all 8 DRAM streams for the whole kernel —
// steadier per-channel load, no A->B phase transition. Everything else
// identical to the 43.5us winner (float4, __ldg, plain stores, 512 thr).
//
//   pair A: (r0, m1) -> out0r = c*r0 + s*m1 ; out1i = c*m1 - s*r0
//   pair B: (r1, m0) -> out1r = c*r1 + s*m0 ; out0i = c*m0 - s*r1

#define NUM_STEPS 20
#define DT_HALF   (0.5f * (1.0f / 20.0f))
#define BATCH     8388608

__global__ __launch_bounds__(512) void grape_kernel(
    const float* __restrict__ amps,
    const float* __restrict__ sr,
    const float* __restrict__ si,
    float* __restrict__ out)
{
    float theta = 0.0f;
#pragma unroll
    for (int k = 0; k < NUM_STEPS; k++) theta += __ldg(&amps[k]);
    theta *= DT_HALF;
    const float c = cosf(theta);
    const float s = sinf(theta);

    // Even blocks -> pair A, odd blocks -> pair B. Within a pair, block
    // pairIdx = blockIdx.x / 2 covers a contiguous 512-float4 chunk.
    const int pairB   = blockIdx.x & 1;
    const int pairIdx = blockIdx.x >> 1;
    const int i       = pairIdx * blockDim.x + threadIdx.x;   // float4 index in row

    const float4* pa;   // multiplied by c in the "+s" output
    const float4* pb;
    float4* po1;        // c*a + s*b
    float4* po2;        // c*b - s*a

    if (!pairB) {
        // pair A: (r0, m1) -> out0r, out1i
        pa  = (const float4*)sr;                          // r0
        pb  = (const float4*)(si + (size_t)BATCH);        // m1
        po1 = (float4*)out;                               // out0r
        po2 = (float4*)(out + 3 * (size_t)BATCH);         // out1i
    } else {
        // pair B: (r1, m0) -> out1r, out0i
        pa  = (const float4*)(sr + (size_t)BATCH);        // r1
        pb  = (const float4*)si;                          // m0
        po1 = (float4*)(out + (size_t)BATCH);             // out1r
        po2 = (float4*)(out + 2 * (size_t)BATCH);         // out0i
    }

    float4 a = __ldg(&pa[i]);
    float4 b = __ldg(&pb[i]);

    float4 o1, o2;
    o1.x = fmaf(c, a.x,  s * b.x);  o2.x = fmaf(c, b.x, -s * a.x);
    o1.y = fmaf(c, a.y,  s * b.y);  o2.y = fmaf(c, b.y, -s * a.y);
    o1.z = fmaf(c, a.z,  s * b.z);  o2.z = fmaf(c, b.z, -s * a.z);
    o1.w = fmaf(c, a.w,  s * b.w);  o2.w = fmaf(c, b.w, -s * a.w);

    po1[i] = o1;
    po2[i] = o2;
}

extern "C" void kernel_launch(void* const* d_in, const int* in_sizes, int n_in,
                              void* d_out, int out_size)
{
    const float* amps = (const float*)d_in[0];  // [20]
    const float* sr   = (const float*)d_in[1];  // [2, B]
    const float* si   = (const float*)d_in[2];  // [2, B]
    float* out        = (float*)d_out;          // [2, 2, B]

    const int n4 = BATCH / 4;                   // 2,097,152 float4 per row
    const int threads = 512;
    const int blocks = (2 * n4) / threads;      // 8192 (even=A, odd=B)
    grape_kernel<<<blocks, threads>>>(amps, sr, si, out);
}